// round 1
// baseline (speedup 1.0000x reference)
#include <cuda_runtime.h>
#include <cstdint>
#include <cstddef>

#define H 256
#define NHEADS 6
#define SEQ 4096
#define G3H 768
#define CLUSTER_N 8

// ---------------- device scratch (no allocs allowed) ----------------
__device__ float g_x[SEQ * H];                       // embedded tokens
__device__ float g_q[NHEADS * SEQ * H];
__device__ float g_k[NHEADS * SEQ * H];
__device__ float g_v[NHEADS * SEQ * H];
__device__ float g_scores[(size_t)NHEADS * SEQ * SEQ];   // 402 MB
__device__ float g_oc[SEQ * NHEADS * H];             // concat attn out [S, 1536]
__device__ float g_y0[SEQ * H];                      // attn projection
__device__ float g_y[SEQ * H];                       // LN output (GRU input)
__device__ float g_gi[SEQ * G3H];                    // precomputed input gates
__device__ float g_hT[H];                            // final hidden

// ---------------- embedding gather ----------------
__global__ void embed_kernel(const int* __restrict__ tok,
                             const float* __restrict__ emb,
                             float* __restrict__ x) {
    int s = blockIdx.x, d = threadIdx.x;
    x[s * H + d] = emb[(size_t)tok[s] * H + d];
}

// ---------------- generic tiled fp32 GEMM ----------------
// C[M,N] = alpha * A[M,K] @ op(B) (+ bias[N]); TRANSB: B is [N,K] row-major.
// batched over blockIdx.z with element strides sA,sB,sBias,sC.
template <bool TRANSB, bool HASBIAS>
__global__ __launch_bounds__(256)
void gemm64(const float* __restrict__ A, const float* __restrict__ B,
            const float* __restrict__ bias, float* __restrict__ C,
            int M, int N, int K, int lda, int ldb, int ldc,
            long long sA, long long sB, long long sBias, long long sC,
            float alpha) {
    __shared__ float As[16][64];
    __shared__ float Bs[16][64];
    int b = blockIdx.z;
    A += (long long)b * sA;
    B += (long long)b * sB;
    C += (long long)b * sC;
    const float* bi = HASBIAS ? (bias + (long long)b * sBias) : nullptr;

    int bm = blockIdx.y * 64, bn = blockIdx.x * 64;
    int tid = threadIdx.x;
    int tx = tid & 15, ty = tid >> 4;

    float acc[4][4];
#pragma unroll
    for (int i = 0; i < 4; i++)
#pragma unroll
        for (int j = 0; j < 4; j++) acc[i][j] = 0.f;

    for (int k0 = 0; k0 < K; k0 += 16) {
        // A tile: As[k][m], read 4 consecutive k per thread
#pragma unroll
        for (int c = 0; c < 4; c++) {
            int idx = tid * 4 + c;
            int m = idx >> 4, kk = idx & 15;
            As[kk][m] = A[(long long)(bm + m) * lda + (k0 + kk)];
        }
        if (TRANSB) {
#pragma unroll
            for (int c = 0; c < 4; c++) {
                int idx = tid * 4 + c;
                int n = idx >> 4, kk = idx & 15;
                Bs[kk][n] = B[(long long)(bn + n) * ldb + (k0 + kk)];
            }
        } else {
#pragma unroll
            for (int c = 0; c < 4; c++) {
                int idx = tid + 256 * c;
                int kk = idx >> 6, n = idx & 63;
                Bs[kk][n] = B[(long long)(k0 + kk) * ldb + (bn + n)];
            }
        }
        __syncthreads();
#pragma unroll
        for (int kk = 0; kk < 16; kk++) {
            float4 a4 = *(const float4*)&As[kk][ty * 4];
            float4 b4 = *(const float4*)&Bs[kk][tx * 4];
            float a[4] = {a4.x, a4.y, a4.z, a4.w};
            float bb[4] = {b4.x, b4.y, b4.z, b4.w};
#pragma unroll
            for (int i = 0; i < 4; i++)
#pragma unroll
                for (int j = 0; j < 4; j++) acc[i][j] += a[i] * bb[j];
        }
        __syncthreads();
    }
#pragma unroll
    for (int i = 0; i < 4; i++) {
        int m = bm + ty * 4 + i;
#pragma unroll
        for (int j = 0; j < 4; j++) {
            int n = bn + tx * 4 + j;
            float v = acc[i][j] * alpha;
            if (HASBIAS) v += bi[n];
            C[(long long)m * ldc + n] = v;
        }
    }
}

// ---------------- row softmax (row length 4096) ----------------
__global__ __launch_bounds__(256)
void softmax_rows(float* __restrict__ S_) {
    float* row = S_ + (size_t)blockIdx.x * SEQ;
    int t = threadIdx.x;
    __shared__ float red[256];
    float vals[16];
    float vmax = -1e30f;
#pragma unroll
    for (int i = 0; i < 16; i++) {
        vals[i] = row[t + i * 256];
        vmax = fmaxf(vmax, vals[i]);
    }
    red[t] = vmax;
    __syncthreads();
    for (int s = 128; s > 0; s >>= 1) {
        if (t < s) red[t] = fmaxf(red[t], red[t + s]);
        __syncthreads();
    }
    vmax = red[0];
    __syncthreads();
    float sum = 0.f;
#pragma unroll
    for (int i = 0; i < 16; i++) {
        vals[i] = __expf(vals[i] - vmax);
        sum += vals[i];
    }
    red[t] = sum;
    __syncthreads();
    for (int s = 128; s > 0; s >>= 1) {
        if (t < s) red[t] += red[t + s];
        __syncthreads();
    }
    float inv = 1.0f / red[0];
#pragma unroll
    for (int i = 0; i < 16; i++) row[t + i * 256] = vals[i] * inv;
}

// ---------------- residual + LayerNorm ----------------
__global__ __launch_bounds__(256)
void add_ln(const float* __restrict__ x, const float* __restrict__ y0,
            const float* __restrict__ gam, const float* __restrict__ bet,
            float* __restrict__ y) {
    int s = blockIdx.x, t = threadIdx.x;
    float v = x[s * H + t] + y0[s * H + t];
    __shared__ float red[256];
    red[t] = v;
    __syncthreads();
    for (int k = 128; k > 0; k >>= 1) {
        if (t < k) red[t] += red[t + k];
        __syncthreads();
    }
    float mu = red[0] * (1.0f / H);
    __syncthreads();
    float d = v - mu;
    red[t] = d * d;
    __syncthreads();
    for (int k = 128; k > 0; k >>= 1) {
        if (t < k) red[t] += red[t + k];
        __syncthreads();
    }
    float var = red[0] * (1.0f / H);
    y[s * H + t] = d * rsqrtf(var + 1e-5f) * gam[t] + bet[t];
}

// ---------------- GRU: 8-CTA cluster, weights in registers ----------------
// CTA `rank` owns hidden units [rank*32, rank*32+32). 256 threads:
// thread = (g, s), g=0..31 unit-within-CTA, s=0..7 32-wide column segment.
// Each thread holds W_hh rows {u, 256+u, 512+u} restricted to its 32 columns
// (8 float4, rotated by s for conflict-free SMEM h reads).
__global__ void __cluster_dims__(CLUSTER_N, 1, 1) __launch_bounds__(256, 1)
gru_kernel(const float* __restrict__ gi, const float* __restrict__ W_hh,
           const float* __restrict__ b_hh, float* __restrict__ hT) {
    __shared__ __align__(16) float hbuf[2][H];
    uint32_t rank;
    asm("mov.u32 %0, %%cluster_ctarank;" : "=r"(rank));
    int t = threadIdx.x;
    int g = t >> 3;
    int s_ = t & 7;
    int u = rank * 32 + g;

    float4 w[3][8];
#pragma unroll
    for (int r = 0; r < 3; r++) {
        const float4* Wrow = (const float4*)(W_hh + (size_t)(r * 256 + u) * H);
#pragma unroll
        for (int j = 0; j < 8; j++) {
            int jj = (j + s_) & 7;
            w[r][j] = Wrow[s_ * 8 + jj];
        }
    }
    float bhr = 0.f, bhz = 0.f, bhn = 0.f;
    if (s_ == 0) {
        bhr = b_hh[u];
        bhz = b_hh[256 + u];
        bhn = b_hh[512 + u];
    }
    if (t < H) { hbuf[0][t] = 0.f; hbuf[1][t] = 0.f; }

    // map our hbuf base into every cluster CTA's SMEM
    uint32_t local_base;
    {
        void* p = (void*)hbuf;
        asm("{ .reg .u64 tt; cvta.to.shared.u64 tt, %1; cvt.u32.u64 %0, tt; }"
            : "=r"(local_base) : "l"(p));
    }
    uint32_t peer_addr[CLUSTER_N];
#pragma unroll
    for (int d = 0; d < CLUSTER_N; d++) {
        asm("mapa.shared::cluster.u32 %0, %1, %2;"
            : "=r"(peer_addr[d]) : "r"(local_base), "r"(d));
    }

    asm volatile("barrier.cluster.arrive.aligned;" ::: "memory");
    asm volatile("barrier.cluster.wait.aligned;" ::: "memory");

    for (int step = 0; step < SEQ; step++) {
        int p = step & 1;
        float gir = 0.f, giz = 0.f, gin = 0.f;
        if (s_ == 0) {  // prefetch early: ~300cyc of dot-product below hides it
            const float* gr = gi + (size_t)step * G3H;
            gir = __ldg(gr + u);
            giz = __ldg(gr + 256 + u);
            gin = __ldg(gr + 512 + u);
        }
        float ar = 0.f, az = 0.f, an = 0.f;
        const float4* h4 = (const float4*)hbuf[p];
#pragma unroll
        for (int j = 0; j < 8; j++) {
            int jj = (j + s_) & 7;
            float4 hv = h4[s_ * 8 + jj];
            ar += hv.x * w[0][j].x + hv.y * w[0][j].y + hv.z * w[0][j].z + hv.w * w[0][j].w;
            az += hv.x * w[1][j].x + hv.y * w[1][j].y + hv.z * w[1][j].z + hv.w * w[1][j].w;
            an += hv.x * w[2][j].x + hv.y * w[2][j].y + hv.z * w[2][j].z + hv.w * w[2][j].w;
        }
#pragma unroll
        for (int off = 4; off > 0; off >>= 1) {
            ar += __shfl_down_sync(0xffffffffu, ar, off);
            az += __shfl_down_sync(0xffffffffu, az, off);
            an += __shfl_down_sync(0xffffffffu, an, off);
        }
        if (s_ == 0) {
            float r = 1.f / (1.f + __expf(-(gir + ar + bhr)));
            float z = 1.f / (1.f + __expf(-(giz + az + bhz)));
            float n = tanhf(gin + r * (an + bhn));
            float hp = hbuf[p][u];
            float h2 = (1.f - z) * n + z * hp;
            uint32_t off = (uint32_t)(((p ^ 1) * H + u) * 4);
            uint32_t h2b = __float_as_uint(h2);
#pragma unroll
            for (int d = 0; d < CLUSTER_N; d++) {
                asm volatile("st.shared::cluster.u32 [%0], %1;"
                             :: "r"(peer_addr[d] + off), "r"(h2b));
            }
        }
        asm volatile("barrier.cluster.arrive.aligned;" ::: "memory");
        asm volatile("barrier.cluster.wait.aligned;" ::: "memory");
    }
    // SEQ even -> final h lives in hbuf[0]
    if (t < 32) hT[rank * 32 + t] = hbuf[0][rank * 32 + t];
}

// ---------------- output copy ----------------
__global__ void write_out(const float* __restrict__ hT, float* __restrict__ out,
                          int n) {
    int i = blockIdx.x * 256 + threadIdx.x;
    if (i < n) out[i] = hT[i & (H - 1)];
}

// ---------------- host launcher ----------------
extern "C" void kernel_launch(void* const* d_in, const int* in_sizes, int n_in,
                              void* d_out, int out_size) {
    const int* tokens = (const int*)d_in[0];
    const float* emb = (const float*)d_in[1];
    const float* Wq = (const float*)d_in[2];
    const float* bq = (const float*)d_in[3];
    const float* Wk = (const float*)d_in[4];
    const float* bk = (const float*)d_in[5];
    const float* Wv = (const float*)d_in[6];
    const float* bv = (const float*)d_in[7];
    const float* Wo = (const float*)d_in[8];
    const float* bo = (const float*)d_in[9];
    const float* ln_g = (const float*)d_in[10];
    const float* ln_b = (const float*)d_in[11];
    const float* W_ih = (const float*)d_in[12];
    const float* W_hh = (const float*)d_in[13];
    const float* b_ih = (const float*)d_in[14];
    const float* b_hh = (const float*)d_in[15];

    void* p;
    float *px, *pq, *pk, *pv, *ps, *poc, *py0, *py, *pgi, *phT;
    cudaGetSymbolAddress(&p, g_x); px = (float*)p;
    cudaGetSymbolAddress(&p, g_q); pq = (float*)p;
    cudaGetSymbolAddress(&p, g_k); pk = (float*)p;
    cudaGetSymbolAddress(&p, g_v); pv = (float*)p;
    cudaGetSymbolAddress(&p, g_scores); ps = (float*)p;
    cudaGetSymbolAddress(&p, g_oc); poc = (float*)p;
    cudaGetSymbolAddress(&p, g_y0); py0 = (float*)p;
    cudaGetSymbolAddress(&p, g_y); py = (float*)p;
    cudaGetSymbolAddress(&p, g_gi); pgi = (float*)p;
    cudaGetSymbolAddress(&p, g_hT); phT = (float*)p;

    const long long SH = (long long)SEQ * H;
    const long long SS = (long long)SEQ * SEQ;
    const float inv_scale = 1.0f / 16.0f;  // 1/sqrt(256)

    // 1) embedding
    embed_kernel<<<SEQ, H>>>(tokens, emb, px);

    // 2) per-head Q/K/V projections (NN, batched over heads)
    dim3 gqkv(H / 64, SEQ / 64, NHEADS);
    gemm64<false, true><<<gqkv, 256>>>(px, Wq, bq, pq, SEQ, H, H, H, H, H,
                                       0, (long long)H * H, H, SH, 1.f);
    gemm64<false, true><<<gqkv, 256>>>(px, Wk, bk, pk, SEQ, H, H, H, H, H,
                                       0, (long long)H * H, H, SH, 1.f);
    gemm64<false, true><<<gqkv, 256>>>(px, Wv, bv, pv, SEQ, H, H, H, H, H,
                                       0, (long long)H * H, H, SH, 1.f);

    // 3) scores = Q @ K^T / sqrt(H)  (NT, batched over heads)
    dim3 gsc(SEQ / 64, SEQ / 64, NHEADS);
    gemm64<true, false><<<gsc, 256>>>(pq, pk, nullptr, ps, SEQ, SEQ, H,
                                      H, H, SEQ, SH, SH, 0, SS, inv_scale);

    // 4) softmax over rows
    softmax_rows<<<NHEADS * SEQ, 256>>>(ps);

    // 5) O = A @ V, written directly into concat layout [S, NH*H]
    dim3 gav(H / 64, SEQ / 64, NHEADS);
    gemm64<false, false><<<gav, 256>>>(ps, pv, nullptr, poc, SEQ, H, SEQ,
                                       SEQ, H, NHEADS * H, SS, SH, 0,
                                       (long long)H, 1.f);

    // 6) output projection [S,1536]@[1536,256]+bo
    dim3 gop(H / 64, SEQ / 64, 1);
    gemm64<false, true><<<gop, 256>>>(poc, Wo, bo, py0, SEQ, H, NHEADS * H,
                                      NHEADS * H, H, H, 0, 0, 0, 0, 1.f);

    // 7) residual + LayerNorm
    add_ln<<<SEQ, H>>>(px, py0, ln_g, ln_b, py);

    // 8) GRU input gates gi = y @ W_ih^T + b_ih  (NT)
    dim3 ggi(G3H / 64, SEQ / 64, 1);
    gemm64<true, true><<<ggi, 256>>>(py, W_ih, b_ih, pgi, SEQ, G3H, H,
                                     H, H, G3H, 0, 0, 0, 0, 1.f);

    // 9) sequential GRU across 8-CTA cluster
    gru_kernel<<<CLUSTER_N, 256>>>(pgi, W_hh, b_hh, phT);

    // 10) write output (reference returns (out, out) -> h replicated)
    write_out<<<(out_size + 255) / 256, 256>>>(phT, (float*)d_out, out_size);
}